// round 3
// baseline (speedup 1.0000x reference)
#include <cuda_runtime.h>
#include <cuda_bf16.h>
#include <cstdint>

// ---------------- problem constants ----------------
#define B_ROWS   8192
#define DFEAT    128
#define DKEEP    64
#define TILE     128
#define NTILES   64
#define NTHREADS 256

#define LOG2E 1.4426950408889634f
#define LN2   0.6931471805599453f
#define SHIFTB 32.0f

// smem byte offsets (dynamic smem)
#define SB_X   0
#define SB_Y0  16384
#define SB_Y1  32768
#define SB_RED 49152
#define SMEM_BYTES 49216

// ---------------- scratch (bf16 gathered matrices) ----------------
__device__ __nv_bfloat16 g_ao [B_ROWS * DKEEP];  // a[:, ai]
__device__ __nv_bfloat16 g_iao[B_ROWS * DKEEP];  // v[:, ai]
__device__ __nv_bfloat16 g_io [B_ROWS * DKEEP];  // v[:, ii]
__device__ __nv_bfloat16 g_aio[B_ROWS * DKEEP];  // a[:, ii]

// ---------------- helpers ----------------
__device__ __forceinline__ uint32_t smem_u32(const void* p) {
    uint32_t a;
    asm("{ .reg .u64 t; cvta.to.shared.u64 t, %1; cvt.u32.u64 %0, t; }" : "=r"(a) : "l"(p));
    return a;
}

__device__ __forceinline__ void cp16(uint32_t dst, const void* src) {
    asm volatile("cp.async.cg.shared.global [%0], [%1], 16;" :: "r"(dst), "l"(src));
}
#define CP_COMMIT() asm volatile("cp.async.commit_group;" ::: "memory")
#define CP_WAIT(n)  asm volatile("cp.async.wait_group %0;" :: "n"(n) : "memory")

__device__ __forceinline__ void ldsm4(uint32_t r[4], uint32_t a) {
    asm volatile("ldmatrix.sync.aligned.m8n8.x4.shared.b16 {%0,%1,%2,%3}, [%4];"
        : "=r"(r[0]), "=r"(r[1]), "=r"(r[2]), "=r"(r[3]) : "r"(a));
}

__device__ __forceinline__ void mma16816(float c[4], const uint32_t a[4],
                                         uint32_t b0, uint32_t b1) {
    asm volatile(
        "mma.sync.aligned.m16n8k16.row.col.f32.bf16.bf16.f32 "
        "{%0,%1,%2,%3}, {%4,%5,%6,%7}, {%8,%9}, {%0,%1,%2,%3};"
        : "+f"(c[0]), "+f"(c[1]), "+f"(c[2]), "+f"(c[3])
        : "r"(a[0]), "r"(a[1]), "r"(a[2]), "r"(a[3]), "r"(b0), "r"(b1));
}

__device__ __forceinline__ float ex2f(float t) {
    float e;
    asm("ex2.approx.ftz.f32 %0, %1;" : "=f"(e) : "f"(t));
    return e;
}

// exp-accumulate one quarter (4 frags) of a register tile
__device__ __forceinline__ void exp_chunk(const float (&prev)[16][4], int kk,
                                          bool dtile, int lane, int row0,
                                          float (&ps)[4], float& dg0, float& dg1) {
#pragma unroll
    for (int fi = 0; fi < 4; fi++) {
        const int f = 4 * kk + fi;
#pragma unroll
        for (int c = 0; c < 4; c++) {
            float sv = prev[f][c];
            if (dtile) {
                int col = 8 * f + 2 * (lane & 3) + (c & 1);
                if (c < 2) { if (col == row0)     dg0 = sv; }
                else       { if (col == row0 + 8) dg1 = sv; }
            }
            ps[c] += ex2f(fmaf(sv, LOG2E, -SHIFTB));
        }
    }
}

// compute tile j into cur, exp-process prev (tile j-1) interleaved
__device__ __forceinline__ void do_tile(
    int j, int rt, uint32_t sbY, int lane,
    const uint32_t (&A)[4][4],
    const uint32_t (&browoff)[8], const uint32_t (&bxr)[8], int bko,
    float (&cur)[16][4], float (&prev)[16][4],
    float (&ps)[4], float& dg0, float& dg1, int row0)
{
#pragma unroll
    for (int f = 0; f < 16; f++)
#pragma unroll
        for (int c = 0; c < 4; c++) cur[f][c] = 0.f;
    const bool dtile = ((j - 1) == rt);
#pragma unroll
    for (int kk = 0; kk < 4; kk++) {
        uint32_t Bf[8][4];
#pragma unroll
        for (int nn = 0; nn < 8; nn++) {
            uint32_t addr = sbY + browoff[nn] + (((uint32_t)((kk << 1) + bko) ^ bxr[nn]) << 4);
            ldsm4(Bf[nn], addr);
        }
#pragma unroll
        for (int nn = 0; nn < 8; nn++) {
            mma16816(cur[2 * nn],     A[kk], Bf[nn][0], Bf[nn][1]);
            mma16816(cur[2 * nn + 1], A[kk], Bf[nn][2], Bf[nn][3]);
        }
        // overlap: MUFU work of previous tile between HMMA batches
        exp_chunk(prev, kk, dtile, lane, row0, ps, dg0, dg1);
    }
}

// ---------------- kernels ----------------
__global__ void zero_out_kernel(float* out, int n) {
    int i = blockIdx.x * blockDim.x + threadIdx.x;
    if (i < n) out[i] = 0.0f;
}

// Index buffers may be int32 (JAX x64 disabled) or int64. Sniff: if every odd
// int32 word of BOTH buffers' first 64 words is zero, values are int64
// (indices < 128 => high words 0). Reads stay within 256B = in-bounds for both
// interpretations. Indices masked &127 so a misdetect can never fault.
__global__ void gather_kernel(const float* __restrict__ a, const float* __restrict__ v,
                              const int* __restrict__ ai32,
                              const int* __restrict__ ii32) {
    __shared__ int sai[DKEEP], sii[DKEEP];
    __shared__ int is64;
    const int tid = threadIdx.x;
    if (tid == 0) {
        int orr = 0;
#pragma unroll
        for (int k = 0; k < 32; k++) orr |= ai32[2 * k + 1] | ii32[2 * k + 1];
        is64 = (orr == 0) ? 1 : 0;
    }
    __syncthreads();
    if (tid < DKEEP) {
        int step = is64 ? 2 : 1;
        sai[tid] = ai32[tid * step] & (DFEAT - 1);
        sii[tid] = ii32[tid * step] & (DFEAT - 1);
    }
    __syncthreads();

    int t = blockIdx.x * blockDim.x + tid;
    int r = t >> 6, k = t & 63;
    int ia = sai[k];
    int iv = sii[k];
    const float* ar = a + (size_t)r * DFEAT;
    const float* vr = v + (size_t)r * DFEAT;
    g_ao [t] = __float2bfloat16(ar[ia]);
    g_iao[t] = __float2bfloat16(vr[ia]);
    g_io [t] = __float2bfloat16(vr[iv]);
    g_aio[t] = __float2bfloat16(ar[iv]);
}

__global__ void __launch_bounds__(NTHREADS, 1)
supcon_main_kernel(float* __restrict__ out) {
    extern __shared__ char smem[];
    const uint32_t sb = smem_u32(smem);
    const int tid  = threadIdx.x;
    const int lane = tid & 31;
    const int wid  = tid >> 5;
    const int m  = blockIdx.x >> 6;   // 0: S_v, 1: S_a
    const int rt = blockIdx.x & 63;   // row tile

    const __nv_bfloat16* X = m ? g_aio : g_iao;
    const __nv_bfloat16* Y = m ? g_io  : g_ao;
    const char* Yb = (const char*)Y;

    // per-thread swizzled 16B-chunk store offsets (u = tid + k*256)
    uint32_t dsto[4];
#pragma unroll
    for (int k = 0; k < 4; k++) {
        uint32_t u = (uint32_t)tid + k * 256u;
        dsto[k] = (u & ~7u) * 16u + (((u & 7u) ^ ((u >> 3) & 7u)) << 4);
    }

    // prefetch Y tiles 0, 1 via cp.async
#pragma unroll
    for (int k = 0; k < 4; k++)
        cp16(sb + SB_Y0 + dsto[k], Yb + (size_t)(tid + k * 256) * 16);
    CP_COMMIT();
#pragma unroll
    for (int k = 0; k < 4; k++)
        cp16(sb + SB_Y1 + dsto[k], Yb + 16384 + (size_t)(tid + k * 256) * 16);
    CP_COMMIT();

    // X tile -> smem (swizzled)
    {
        const uint4* xg = (const uint4*)(X + (size_t)rt * TILE * DKEEP);
#pragma unroll
        for (int k = 0; k < 4; k++) {
            uint4 val = xg[tid + k * 256];
            *(uint4*)(smem + SB_X + dsto[k]) = val;
        }
    }
    __syncthreads();

    // A fragments (held in registers for the whole kernel)
    uint32_t A[4][4];
    {
        int row = 16 * wid + (lane & 15);
        int kc  = lane >> 4;  // 0/1 -> k halves
#pragma unroll
        for (int kk = 0; kk < 4; kk++) {
            uint32_t chunk = (uint32_t)(kk * 2 + kc);
            uint32_t addr  = sb + SB_X + (uint32_t)row * 128u + ((chunk ^ (uint32_t)(row & 7)) << 4);
            ldsm4(A[kk], addr);
        }
    }

    // B ldmatrix address row parts
    uint32_t browoff[8], bxr[8];
    const int bn  = ((lane >> 4) << 3) + (lane & 7);
    const int bko = (lane >> 3) & 1;
#pragma unroll
    for (int nn = 0; nn < 8; nn++) {
        int nr = 16 * nn + bn;
        browoff[nn] = (uint32_t)nr * 128u;
        bxr[nn] = (uint32_t)(nr & 7);
    }

    float accC[16][4], accP[16][4];
#pragma unroll
    for (int f = 0; f < 16; f++)
#pragma unroll
        for (int c = 0; c < 4; c++) accP[f][c] = -1e30f;   // exp -> 0 on first tile
    float ps[4] = {0.f, 0.f, 0.f, 0.f};
    float dg0 = 0.f, dg1 = 0.f;
    const int row0 = 16 * wid + (lane >> 2);

    for (int jj = 0; jj < NTILES; jj += 2) {
        // ---- even tile jj : stage 0, cur=accC, prev=accP ----
        CP_WAIT(1);
        __syncthreads();
        do_tile(jj, rt, sb + SB_Y0, lane, A, browoff, bxr, bko,
                accC, accP, ps, dg0, dg1, row0);
        __syncthreads();
        if (jj + 2 < NTILES) {
            const char* src = Yb + (size_t)(jj + 2) * 16384;
#pragma unroll
            for (int k = 0; k < 4; k++)
                cp16(sb + SB_Y0 + dsto[k], src + (size_t)(tid + k * 256) * 16);
            CP_COMMIT();
        }
        // ---- odd tile jj+1 : stage 1, cur=accP, prev=accC ----
        if (jj + 1 == NTILES - 1) { CP_WAIT(0); } else { CP_WAIT(1); }
        __syncthreads();
        do_tile(jj + 1, rt, sb + SB_Y1, lane, A, browoff, bxr, bko,
                accP, accC, ps, dg0, dg1, row0);
        __syncthreads();
        if (jj + 3 < NTILES) {
            const char* src = Yb + (size_t)(jj + 3) * 16384;
#pragma unroll
            for (int k = 0; k < 4; k++)
                cp16(sb + SB_Y1 + dsto[k], src + (size_t)(tid + k * 256) * 16);
            CP_COMMIT();
        }
    }

    // tail: exp-process the last tile (63, sitting in accP)
    {
        const bool dtile = (rt == NTILES - 1);
#pragma unroll
        for (int kk = 0; kk < 4; kk++)
            exp_chunk(accP, kk, dtile, lane, row0, ps, dg0, dg1);
    }

    // ---- reduction ----
    float rs0 = ps[0] + ps[1];
    float rs1 = ps[2] + ps[3];
    rs0 += __shfl_xor_sync(0xffffffffu, rs0, 1);
    rs0 += __shfl_xor_sync(0xffffffffu, rs0, 2);
    rs1 += __shfl_xor_sync(0xffffffffu, rs1, 1);
    rs1 += __shfl_xor_sync(0xffffffffu, rs1, 2);
    dg0 += __shfl_xor_sync(0xffffffffu, dg0, 1);
    dg0 += __shfl_xor_sync(0xffffffffu, dg0, 2);
    dg1 += __shfl_xor_sync(0xffffffffu, dg1, 1);
    dg1 += __shfl_xor_sync(0xffffffffu, dg1, 2);

    float loss = 0.f;
    if ((lane & 3) == 0) {
        float l0, l1;
        asm("lg2.approx.f32 %0, %1;" : "=f"(l0) : "f"(rs0));
        asm("lg2.approx.f32 %0, %1;" : "=f"(l1) : "f"(rs1));
        loss = (l0 + SHIFTB) * LN2 - dg0 + (l1 + SHIFTB) * LN2 - dg1;
    }
#pragma unroll
    for (int o = 4; o < 32; o <<= 1)
        loss += __shfl_xor_sync(0xffffffffu, loss, o);

    float* red = (float*)(smem + SB_RED);
    if (lane == 0) red[wid] = loss;
    __syncthreads();
    if (tid == 0) {
        float t = 0.f;
#pragma unroll
        for (int w = 0; w < 8; w++) t += red[w];
        atomicAdd(out, t * (1.0f / (float)B_ROWS));
    }
}

// ---------------- launch ----------------
extern "C" void kernel_launch(void* const* d_in, const int* in_sizes, int n_in,
                              void* d_out, int out_size) {
    const float* a = (const float*)d_in[0];
    const float* v = (const float*)d_in[1];
    const int* ai = (const int*)d_in[2];
    const int* ii = (const int*)d_in[3];
    float* out = (float*)d_out;

    cudaFuncSetAttribute(supcon_main_kernel,
                         cudaFuncAttributeMaxDynamicSharedMemorySize, SMEM_BYTES);

    zero_out_kernel<<<(out_size + 255) / 256, 256>>>(out, out_size);
    gather_kernel<<<(B_ROWS * DKEEP) / 256, 256>>>(a, v, ai, ii);
    supcon_main_kernel<<<128, NTHREADS, SMEM_BYTES>>>(out);
}